// round 6
// baseline (speedup 1.0000x reference)
#include <cuda_runtime.h>
#include <cstdint>

// Shapes (fixed): B=8, L=2048, H=256
// in:  d_in[0] g    [8,2048,256] f32
//      d_in[1] WP   [256,256]    f32   (out,in)
//      d_in[2] Wout [256,768]    f32   (out,in)
//      d_in[3] bout [256]        f32
// out: [8,2048,256] f32

#define TPB 256
constexpr int BM = 128, BN = 128, BK = 8;

// Scratch (static device globals — no allocations).
static __device__ float g_WPT[256 * 256];            // WP^T          (256 KB)
static __device__ float g_gT [8 * 256 * 2048];       // g^T  [b,h,j]  (16 MB)
static __device__ float g_WhT[8 * 256 * 2048];       // Wh^T [b,h,i]  (16 MB)
static __device__ float g_c  [8 * 2048 * 256];       // c    [b,i,h]  (16 MB)
static __device__ float g_P  [33554432];             // P    [b,j,i]  (128 MB)

// ---------------------------------------------------------------------------
// cp.async helpers (LDGSTS.128)
// ---------------------------------------------------------------------------
__device__ __forceinline__ void cp_async16(void* smem_dst, const void* gmem_src)
{
    uint32_t dst = (uint32_t)__cvta_generic_to_shared(smem_dst);
    asm volatile("cp.async.ca.shared.global [%0], [%1], 16;" :: "r"(dst), "l"(gmem_src));
}
__device__ __forceinline__ void cp_async_commit()
{
    asm volatile("cp.async.commit_group;");
}
template <int N>
__device__ __forceinline__ void cp_async_wait()
{
    asm volatile("cp.async.wait_group %0;" :: "n"(N));
}

// ---------------------------------------------------------------------------
// Batched 32x32 tiled transpose: in [R,C] row-major -> out [C,R] row-major.
// R, C multiples of 32. Block (32,8), 4 rows per thread. Conflict-free smem.
// ---------------------------------------------------------------------------
__global__ __launch_bounds__(256) void transpose_k(
    const float* __restrict__ in, float* __restrict__ out,
    int R, int C, long long sIn, long long sOut)
{
    in  += (long long)blockIdx.z * sIn;
    out += (long long)blockIdx.z * sOut;

    __shared__ float tile[32][33];
    const int x = blockIdx.x * 32 + threadIdx.x;   // col in 'in'
    const int y0 = blockIdx.y * 32 + threadIdx.y;  // row in 'in'
#pragma unroll
    for (int i = 0; i < 32; i += 8)
        tile[threadIdx.y + i][threadIdx.x] = in[(long long)(y0 + i) * C + x];
    __syncthreads();
    const int ox = blockIdx.y * 32 + threadIdx.x;  // col in 'out' (= row in 'in')
    const int oy0 = blockIdx.x * 32 + threadIdx.y; // row in 'out' (= col in 'in')
#pragma unroll
    for (int i = 0; i < 32; i += 8)
        out[(long long)(oy0 + i) * R + ox] = tile[threadIdx.x][threadIdx.y + i];
}

// ---------------------------------------------------------------------------
// 8x8 micro-kernel over one BK-deep smem tile, using packed fp32 FMA
// (fma.rn.f32x2 — FFMA2 in SASS; ptxas never emits it from C++).
// Accumulator acc[i][jp]: column pairs 0,1 -> cols tx*4+{0..3}; pairs 2,3 ->
// cols 64+tx*4+{0..3}. Rows: i<4 -> ty*4+i, i>=4 -> 64+ty*4+(i-4).
// B-fragments read from smem as 64-bit halves of an LDS.128 (conflict-free:
// tx*16B -> banks 0,4,...,28 per phase); A-fragments broadcast.
// Arithmetic is bitwise identical to scalar FFMA (each half is IEEE RN FMA).
// ---------------------------------------------------------------------------
__device__ __forceinline__ void mk_compute(
    const float (*As)[BM + 4], const float (*Bs)[BN + 4],
    int ty, int tx, unsigned long long acc[8][4])
{
#pragma unroll
    for (int kk = 0; kk < BK; kk++) {
        float4 a0 = *(const float4*)&As[kk][ty * 4];
        float4 a1 = *(const float4*)&As[kk][64 + ty * 4];
        ulonglong2 bq0 = *(const ulonglong2*)&Bs[kk][tx * 4];
        ulonglong2 bq1 = *(const ulonglong2*)&Bs[kk][64 + tx * 4];
        unsigned long long bp[4] = {bq0.x, bq0.y, bq1.x, bq1.y};
        float ar[8] = {a0.x, a0.y, a0.z, a0.w, a1.x, a1.y, a1.z, a1.w};
#pragma unroll
        for (int i = 0; i < 8; i++) {
            unsigned long long ab;
            asm("mov.b64 %0, {%1, %1};" : "=l"(ab) : "r"(__float_as_uint(ar[i])));
#pragma unroll
            for (int jp = 0; jp < 4; jp++) {
                asm("fma.rn.f32x2 %0, %1, %2, %0;"
                    : "+l"(acc[i][jp]) : "l"(ab), "l"(bp[jp]));
            }
        }
    }
}

// Epilogue: unpack f32x2 accumulators and store (optional bias+relu).
__device__ __forceinline__ void mk_store(
    float* C, int N, int row_base, int col_base, int ty, int tx,
    const unsigned long long acc[8][4], const float* bias, bool relu)
{
#pragma unroll
    for (int ih = 0; ih < 2; ih++) {
#pragma unroll
        for (int i = 0; i < 4; i++) {
            const int ai = ih * 4 + i;
            long long r = (long long)(row_base + ih * 64 + ty * 4 + i) * N;
#pragma unroll
            for (int jh = 0; jh < 2; jh++) {
                const int cb = col_base + jh * 64 + tx * 4;
                unsigned int u0, u1, u2, u3;
                asm("mov.b64 {%0, %1}, %2;" : "=r"(u0), "=r"(u1) : "l"(acc[ai][jh * 2 + 0]));
                asm("mov.b64 {%0, %1}, %2;" : "=r"(u2), "=r"(u3) : "l"(acc[ai][jh * 2 + 1]));
                float v0 = __uint_as_float(u0), v1 = __uint_as_float(u1);
                float v2 = __uint_as_float(u2), v3 = __uint_as_float(u3);
                if (bias) {
                    v0 += bias[cb + 0]; v1 += bias[cb + 1];
                    v2 += bias[cb + 2]; v3 += bias[cb + 3];
                }
                if (relu) {
                    v0 = fmaxf(v0, 0.f); v1 = fmaxf(v1, 0.f);
                    v2 = fmaxf(v2, 0.f); v3 = fmaxf(v3, 0.f);
                }
                *(float4*)(C + r + cb) = make_float4(v0, v1, v2, v3);
            }
        }
    }
}

// ---------------------------------------------------------------------------
// TN GEMM: C[m,n] = sum_k A[k,m] * B[k,n]  (A:[K,M] rm, B:[K,N] rm, C:[M,N] rm)
// Gmem tiles are contiguous-in-m for fixed k -> straight 16B copies ->
// 3-stage cp.async pipeline. Buffer reused 3 tiles later; the WAR on the copy
// target is covered by the barrier of the intervening iteration.
// All GEMMs in the chain use this kernel (operands pre-transposed as needed).
// ---------------------------------------------------------------------------
__global__ __launch_bounds__(TPB) void gemm_tn(
    const float* __restrict__ A, const float* __restrict__ B, float* __restrict__ C,
    int M, int N, int K, long long sA, long long sB, long long sC)
{
    A += (long long)blockIdx.z * sA;
    B += (long long)blockIdx.z * sB;
    C += (long long)blockIdx.z * sC;

    __shared__ __align__(16) float As[3][BK][BM + 4];
    __shared__ __align__(16) float Bs[3][BK][BN + 4];

    const int tid = threadIdx.x;
    const int lk = tid >> 5;            // 0..7
    const int lm = (tid & 31) << 2;     // 0,4,...,124
    const int tx = tid & 15, ty = tid >> 4;

    const float* Ald = A + (long long)lk * M + blockIdx.y * BM + lm;
    const float* Bld = B + (long long)lk * N + blockIdx.x * BN + lm;

    unsigned long long acc[8][4];
#pragma unroll
    for (int i = 0; i < 8; i++)
#pragma unroll
        for (int j = 0; j < 4; j++) acc[i][j] = 0ULL;

    const int T = K / BK;               // k-tiles (>= 32 for all call sites)

    // Prologue: stage tiles 0 and 1.
    cp_async16(&As[0][lk][lm], Ald);
    cp_async16(&Bs[0][lk][lm], Bld);
    cp_async_commit();
    cp_async16(&As[1][lk][lm], Ald + (long long)BK * M);
    cp_async16(&Bs[1][lk][lm], Bld + (long long)BK * N);
    cp_async_commit();

    int buf = 0;
    for (int t = 0; t < T; t++) {
        if (t + 2 < T) {                // issue tile t+2 into buffer (t+2)%3
            const int nb = (buf + 2 >= 3) ? buf - 1 : buf + 2;
            const long long ko = (long long)(t + 2) * BK;
            cp_async16(&As[nb][lk][lm], Ald + ko * M);
            cp_async16(&Bs[nb][lk][lm], Bld + ko * N);
            cp_async_commit();
            cp_async_wait<2>();         // tile t complete (t+1, t+2 in flight)
        } else if (t + 1 < T) {
            cp_async_wait<1>();
        } else {
            cp_async_wait<0>();
        }
        __syncthreads();
        mk_compute(As[buf], Bs[buf], ty, tx, acc);
        __syncthreads();                // protect buffer reuse by later copies
        buf = (buf + 1 == 3) ? 0 : buf + 1;
    }

    mk_store(C, N, blockIdx.y * BM, blockIdx.x * BN, ty, tx, acc, nullptr, false);
}

// ---------------------------------------------------------------------------
// Row softmax over P: 16384 rows of 2048 contiguous floats, in place.
// (P stores s transposed, so the reference's dim=1 softmax is a row softmax.)
// ---------------------------------------------------------------------------
__global__ __launch_bounds__(TPB) void softmax_rows(float* __restrict__ P)
{
    float4* row = (float4*)(P + (long long)blockIdx.x * 2048);
    const int tid = threadIdx.x;
    float4 v0 = row[tid];
    float4 v1 = row[tid + 256];

    float m = fmaxf(fmaxf(fmaxf(v0.x, v0.y), fmaxf(v0.z, v0.w)),
                    fmaxf(fmaxf(v1.x, v1.y), fmaxf(v1.z, v1.w)));
    __shared__ float red[8];
#pragma unroll
    for (int o = 16; o > 0; o >>= 1) m = fmaxf(m, __shfl_xor_sync(0xffffffffu, m, o));
    if ((tid & 31) == 0) red[tid >> 5] = m;
    __syncthreads();
    float bm = red[0];
#pragma unroll
    for (int i = 1; i < 8; i++) bm = fmaxf(bm, red[i]);
    __syncthreads();

    v0.x = __expf(v0.x - bm); v0.y = __expf(v0.y - bm); v0.z = __expf(v0.z - bm); v0.w = __expf(v0.w - bm);
    v1.x = __expf(v1.x - bm); v1.y = __expf(v1.y - bm); v1.z = __expf(v1.z - bm); v1.w = __expf(v1.w - bm);

    float s = v0.x + v0.y + v0.z + v0.w + v1.x + v1.y + v1.z + v1.w;
#pragma unroll
    for (int o = 16; o > 0; o >>= 1) s += __shfl_xor_sync(0xffffffffu, s, o);
    if ((tid & 31) == 0) red[tid >> 5] = s;
    __syncthreads();
    float bs = 0.f;
#pragma unroll
    for (int i = 0; i < 8; i++) bs += red[i];
    float r = 1.0f / bs;

    v0.x *= r; v0.y *= r; v0.z *= r; v0.w *= r;
    v1.x *= r; v1.y *= r; v1.z *= r; v1.w *= r;
    row[tid] = v0;
    row[tid + 256] = v1;
}

// ---------------------------------------------------------------------------
// Fused output GEMM: out = relu( concat(g, c, g*c) @ Wout^T + b )
// M=16384, N=256, K=768; virtual A-tile built on the fly. Register-staged
// double buffer (A operand is synthesized, so cp.async cannot apply).
// ---------------------------------------------------------------------------
__device__ __forceinline__ float4 load_concat(
    const float* grow, const float* crow, int kg)
{
    if (kg < 256) return *(const float4*)(grow + kg);
    if (kg < 512) return *(const float4*)(crow + kg - 256);
    float4 x = *(const float4*)(grow + kg - 512);
    float4 y = *(const float4*)(crow + kg - 512);
    return make_float4(x.x * y.x, x.y * y.y, x.z * y.z, x.w * y.w);
}

__global__ __launch_bounds__(TPB) void gemm_out_fused(
    const float* __restrict__ g, const float* __restrict__ cbuf,
    const float* __restrict__ W, const float* __restrict__ bias,
    float* __restrict__ out)
{
    __shared__ __align__(16) float As[2][BK][BM + 4];
    __shared__ __align__(16) float Bs[2][BK][BN + 4];

    const int tid = threadIdx.x;
    const int lm = tid >> 1;
    const int lk = (tid & 1) << 2;
    const int tx = tid & 15, ty = tid >> 4;

    const float* grow = g    + (long long)(blockIdx.y * BM + lm) * 256;
    const float* crow = cbuf + (long long)(blockIdx.y * BM + lm) * 256;
    const float* wrow = W    + (long long)(blockIdx.x * BN + lm) * 768 + lk;

    unsigned long long acc[8][4];
#pragma unroll
    for (int i = 0; i < 8; i++)
#pragma unroll
        for (int j = 0; j < 4; j++) acc[i][j] = 0ULL;

    {
        float4 a = load_concat(grow, crow, lk);
        float4 b = *(const float4*)(wrow);
        As[0][lk + 0][lm] = a.x; As[0][lk + 1][lm] = a.y; As[0][lk + 2][lm] = a.z; As[0][lk + 3][lm] = a.w;
        Bs[0][lk + 0][lm] = b.x; Bs[0][lk + 1][lm] = b.y; Bs[0][lk + 2][lm] = b.z; Bs[0][lk + 3][lm] = b.w;
    }
    __syncthreads();

    int buf = 0;
    for (int k0 = 0; k0 < 768; k0 += BK) {
        const bool has_next = (k0 + BK) < 768;
        float4 an, bn;
        if (has_next) {
            an = load_concat(grow, crow, k0 + BK + lk);
            bn = *(const float4*)(wrow + k0 + BK);
        }
        mk_compute(As[buf], Bs[buf], ty, tx, acc);
        if (has_next) {
            const int nb = buf ^ 1;
            As[nb][lk + 0][lm] = an.x; As[nb][lk + 1][lm] = an.y; As[nb][lk + 2][lm] = an.z; As[nb][lk + 3][lm] = an.w;
            Bs[nb][lk + 0][lm] = bn.x; Bs[nb][lk + 1][lm] = bn.y; Bs[nb][lk + 2][lm] = bn.z; Bs[nb][lk + 3][lm] = bn.w;
            __syncthreads();
            buf = nb;
        }
    }

    mk_store(out, 256, blockIdx.y * BM, blockIdx.x * BN, ty, tx, acc, bias, true);
}

// ---------------------------------------------------------------------------
extern "C" void kernel_launch(void* const* d_in, const int* in_sizes, int n_in,
                              void* d_out, int out_size)
{
    const float* g    = (const float*)d_in[0];
    const float* WP   = (const float*)d_in[1];
    const float* Wout = (const float*)d_in[2];
    const float* bout = (const float*)d_in[3];
    float* out = (float*)d_out;

    float *WPT = nullptr, *gT = nullptr, *WhT = nullptr, *c = nullptr, *P = nullptr;
    cudaGetSymbolAddress((void**)&WPT, g_WPT);
    cudaGetSymbolAddress((void**)&gT,  g_gT);
    cudaGetSymbolAddress((void**)&WhT, g_WhT);
    cudaGetSymbolAddress((void**)&c,   g_c);
    cudaGetSymbolAddress((void**)&P,   g_P);

    const long long sG = 2048LL * 256;       // per-batch stride for g/gT/WhT/c
    const long long sP = 2048LL * 2048;      // per-batch stride for P

    // 0a) WPT[h][o] = WP[o][h]
    transpose_k<<<dim3(256 / 32, 256 / 32, 1), dim3(32, 8)>>>(WP, WPT, 256, 256, 0, 0);
    // 0b) gT[b][h][j] = g[b][j][h]
    transpose_k<<<dim3(256 / 32, 2048 / 32, 8), dim3(32, 8)>>>(g, gT, 2048, 256, sG, sG);

    // 1) WhT[b][o][i] = sum_h WPT[h][o] * gT[b][h][i] : M=256, N=2048, K=256
    gemm_tn<<<dim3(2048 / BN, 256 / BM, 8), TPB>>>(WPT, gT, WhT, 256, 2048, 256, 0, sG, sG);

    // 2) P[b][j][i] = sum_h gT[b][h][j] * WhT[b][h][i] : M=N=2048, K=256
    gemm_tn<<<dim3(2048 / BN, 2048 / BM, 8), TPB>>>(gT, WhT, P, 2048, 2048, 256, sG, sG, sP);

    // 3) softmax along i (contiguous rows of P)
    softmax_rows<<<16384, TPB>>>(P);

    // 4) c[b][i][h] = sum_j P[b][j][i] * g[b][j][h] : M=2048, N=256, K=2048
    gemm_tn<<<dim3(256 / BN, 2048 / BM, 8), TPB>>>(P, g, c, 2048, 256, 2048, sP, sG, sG);

    // 5) out = relu(concat(g, c, g*c) @ Wout^T + b) : M=16384, N=256, K=768
    gemm_out_fused<<<dim3(256 / BN, 16384 / BM, 1), TPB>>>(g, c, Wout, bout, out);
}